// round 14
// baseline (speedup 1.0000x reference)
#include <cuda_runtime.h>
#include <cstdint>
#include <cstddef>

#define B_   128
#define P_   625
#define ENC_ 512
#define A_   256
#define E_   256
#define H_   512
#define V_   70
#define T_   70
#define G4_  2048   // 4*H
#define KX_  1280   // E + ENC + H
#define NHP_ 768    // A + H  (att2 | gate-pre)
#define NZH_  8     // hproj partial slots
#define NZG1_ 4     // gates_p1 partial slots (h @ Whh)
#define NZG2_ 8     // gates_p2 partial slots ([emb|awe] @ Wih)
#define NZT_  12    // total gates partial slots
#define NBLK 148
#define ROWS_PER_BLK 541   // ceil(128*625/148)

// ---------------- device scratch (static; no runtime allocation) ----------------
__device__ float g_att1[(size_t)B_ * P_ * A_];   // 81.92 MB fp32 (precision load-bearing)
__device__ float g_e[B_ * P_];
__device__ float g_h[B_ * H_];
__device__ float g_c[B_ * H_];
__device__ float g_xcat[B_ * KX_];               // [emb | awe_gated | h]
__device__ float g_hproj[NZH_ * B_ * NHP_];
__device__ float g_gates[NZT_ * B_ * G4_];       // z 0..3: h@Whh ; z 4..11: [emb|awe]@Wih
__device__ float g_preds[B_ * V_];
__device__ float g_Wcat[(size_t)KX_ * G4_];      // [Wih ; Whh]
__device__ float g_Whb[H_ * NHP_];               // [Wd | Wb]
__device__ float g_WfcT[V_ * H_];
__device__ int   g_done;
__device__ unsigned g_bar_count;
__device__ volatile unsigned g_bar_gen;

// ---------------- helpers ----------------
__device__ __forceinline__ float warp_sum(float v) {
#pragma unroll
  for (int o = 16; o; o >>= 1) v += __shfl_down_sync(0xffffffffu, v, o);
  return v;
}
__device__ __forceinline__ float warp_max(float v) {
#pragma unroll
  for (int o = 16; o; o >>= 1) v = fmaxf(v, __shfl_down_sync(0xffffffffu, v, o));
  return v;
}
__device__ __forceinline__ float sigf(float x) { return 1.f / (1.f + expf(-x)); }

// ---------------- software grid barrier (all NBLK blocks co-resident) ----------------
__device__ __forceinline__ void grid_sync() {
  __syncthreads();
  if (threadIdx.x == 0) {
    __threadfence();
    const unsigned gen = g_bar_gen;
    if (atomicAdd(&g_bar_count, 1u) == NBLK - 1) {
      g_bar_count = 0u;
      __threadfence();
      g_bar_gen = gen + 1u;
    } else {
      while (g_bar_gen == gen) { __nanosleep(32); }
      __threadfence();
    }
  }
  __syncthreads();
}

// ---------------- 256-thread GEMM body (used by one-time att1 GEMM) ----------------
__device__ __forceinline__ void gemm_body(
    const float* __restrict__ A, int lda,
    const float* __restrict__ Bm, int N,
    float* __restrict__ C, const float* __restrict__ bias,
    int kPer, int k0, int mBase, int nBase) {
  const int tid = threadIdx.x;
  __shared__ float As[16][68];
  __shared__ float Bs[16][68];
  const int tm = (tid >> 4) << 2;
  const int tn = (tid & 15) << 2;
  const int lm = tid >> 2;
  const int lk = (tid & 3) << 2;
  const int bk = tid >> 4;
  const int bn = (tid & 15) << 2;
  float acc[4][4] = {};
  for (int kk = 0; kk < kPer; kk += 16) {
    const float4 av = *reinterpret_cast<const float4*>(
        A + (size_t)(mBase + lm) * lda + (k0 + kk + lk));
    const float4 bv = *reinterpret_cast<const float4*>(
        Bm + (size_t)(k0 + kk + bk) * N + (nBase + bn));
    __syncthreads();
    As[lk + 0][lm] = av.x; As[lk + 1][lm] = av.y;
    As[lk + 2][lm] = av.z; As[lk + 3][lm] = av.w;
    Bs[bk][bn + 0] = bv.x; Bs[bk][bn + 1] = bv.y;
    Bs[bk][bn + 2] = bv.z; Bs[bk][bn + 3] = bv.w;
    __syncthreads();
#pragma unroll
    for (int k = 0; k < 16; k++) {
      float a0 = As[k][tm + 0], a1 = As[k][tm + 1], a2 = As[k][tm + 2], a3 = As[k][tm + 3];
      float b0 = Bs[k][tn + 0], b1 = Bs[k][tn + 1], b2 = Bs[k][tn + 2], b3 = Bs[k][tn + 3];
      acc[0][0] = fmaf(a0, b0, acc[0][0]); acc[0][1] = fmaf(a0, b1, acc[0][1]);
      acc[0][2] = fmaf(a0, b2, acc[0][2]); acc[0][3] = fmaf(a0, b3, acc[0][3]);
      acc[1][0] = fmaf(a1, b0, acc[1][0]); acc[1][1] = fmaf(a1, b1, acc[1][1]);
      acc[1][2] = fmaf(a1, b2, acc[1][2]); acc[1][3] = fmaf(a1, b3, acc[1][3]);
      acc[2][0] = fmaf(a2, b0, acc[2][0]); acc[2][1] = fmaf(a2, b1, acc[2][1]);
      acc[2][2] = fmaf(a2, b2, acc[2][2]); acc[2][3] = fmaf(a2, b3, acc[2][3]);
      acc[3][0] = fmaf(a3, b0, acc[3][0]); acc[3][1] = fmaf(a3, b1, acc[3][1]);
      acc[3][2] = fmaf(a3, b2, acc[3][2]); acc[3][3] = fmaf(a3, b3, acc[3][3]);
    }
  }
#pragma unroll
  for (int i = 0; i < 4; i++) {
#pragma unroll
    for (int jj = 0; jj < 4; jj++) {
      const int n = nBase + tn + jj;
      float v = acc[i][jj];
      if (bias) v += bias[n];
      C[(size_t)(mBase + tm + i) * N + n] = v;
    }
  }
}

__global__ void __launch_bounds__(256) gemm64(
    const float* __restrict__ A, int lda, const float* __restrict__ B,
    float* __restrict__ C, const float* __restrict__ bias,
    int M, int N, int K) {
  const int kPer = K / gridDim.z;
  gemm_body(A, lda, B, N, C + (size_t)blockIdx.z * M * N, bias,
            kPer, blockIdx.z * kPer, blockIdx.y * 64, blockIdx.x * 64);
}

// ---------------- 1024-thread GEMM body: 128x128 tile, M fixed = 128 ----------------
__device__ void gemm128(const float* __restrict__ A, int lda,
                        const float* __restrict__ Bm, int N,
                        float* __restrict__ C,
                        int kPer, int k0, int nBase) {
  __shared__ float As[16][136];
  __shared__ float Bs[16][136];
  const int tid = threadIdx.x;
  const int tm = (tid >> 5) << 2;        // 0..124
  const int tn = (tid & 31) << 2;        // 0..124
  const int lm = (tid & 511) >> 2;       // A loader row
  const int lk = (tid & 3) << 2;         // A loader k-offset
  float acc[4][4] = {};
  for (int kk = 0; kk < kPer; kk += 16) {
    __syncthreads();
    if (tid < 512) {
      const float4 av = *reinterpret_cast<const float4*>(
          A + (size_t)lm * lda + (k0 + kk + lk));
      As[lk + 0][lm] = av.x; As[lk + 1][lm] = av.y;
      As[lk + 2][lm] = av.z; As[lk + 3][lm] = av.w;
    } else {
      const int bk = (tid >> 5) - 16;    // 0..15
      *reinterpret_cast<float4*>(&Bs[bk][tn]) =
          *reinterpret_cast<const float4*>(Bm + (size_t)(k0 + kk + bk) * N + (nBase + tn));
    }
    __syncthreads();
#pragma unroll
    for (int k = 0; k < 16; k++) {
      const float4 a = *reinterpret_cast<const float4*>(&As[k][tm]);
      const float4 b = *reinterpret_cast<const float4*>(&Bs[k][tn]);
      acc[0][0] = fmaf(a.x, b.x, acc[0][0]); acc[0][1] = fmaf(a.x, b.y, acc[0][1]);
      acc[0][2] = fmaf(a.x, b.z, acc[0][2]); acc[0][3] = fmaf(a.x, b.w, acc[0][3]);
      acc[1][0] = fmaf(a.y, b.x, acc[1][0]); acc[1][1] = fmaf(a.y, b.y, acc[1][1]);
      acc[1][2] = fmaf(a.y, b.z, acc[1][2]); acc[1][3] = fmaf(a.y, b.w, acc[1][3]);
      acc[2][0] = fmaf(a.z, b.x, acc[2][0]); acc[2][1] = fmaf(a.z, b.y, acc[2][1]);
      acc[2][2] = fmaf(a.z, b.z, acc[2][2]); acc[2][3] = fmaf(a.z, b.w, acc[2][3]);
      acc[3][0] = fmaf(a.w, b.x, acc[3][0]); acc[3][1] = fmaf(a.w, b.y, acc[3][1]);
      acc[3][2] = fmaf(a.w, b.z, acc[3][2]); acc[3][3] = fmaf(a.w, b.w, acc[3][3]);
    }
  }
#pragma unroll
  for (int i = 0; i < 4; i++) {
    *reinterpret_cast<float4*>(C + (size_t)(tm + i) * N + nBase + tn) =
        make_float4(acc[i][0], acc[i][1], acc[i][2], acc[i][3]);
  }
}

// ---------------- one-time prep kernels ----------------
__global__ void prep_weights(const float* __restrict__ Wd, const float* __restrict__ Wb,
                             const float* __restrict__ Wfc) {
  const int idx = blockIdx.x * 256 + threadIdx.x;
  if (idx < H_ * NHP_) {
    const int k = idx / NHP_, n = idx % NHP_;
    g_Whb[idx] = (n < A_) ? Wd[k * A_ + n] : Wb[k * H_ + (n - A_)];
  }
  if (idx < V_ * H_) {
    const int v = idx / H_, k = idx % H_;
    g_WfcT[idx] = Wfc[k * V_ + v];
  }
}

__global__ void init_kernel(const float* __restrict__ emb) {
  const int b = blockIdx.x, i = threadIdx.x;  // 256
  g_xcat[b * KX_ + i] = emb[68 * E_ + i];     // START_TOK = 68
  if (b == 0 && i == 0) { g_done = 0; g_bar_count = 0u; }
}

__global__ void mean_init_kernel(const float* __restrict__ enc,
                                 const float* __restrict__ Wh0, const float* __restrict__ bh0,
                                 const float* __restrict__ Wc0, const float* __restrict__ bc0) {
  const int b = blockIdx.x, e = threadIdx.x;  // 512
  const float* p = enc + (size_t)b * P_ * ENC_ + e;
  float s = 0.f;
#pragma unroll 5
  for (int i = 0; i < P_; i++) s += p[(size_t)i * ENC_];
  __shared__ float ms[ENC_];
  ms[e] = s / 625.f;
  __syncthreads();
  float h = bh0[e], c = bc0[e];
#pragma unroll 4
  for (int k = 0; k < ENC_; k++) {
    const float m = ms[k];
    h = fmaf(m, Wh0[k * H_ + e], h);
    c = fmaf(m, Wc0[k * H_ + e], c);
  }
  g_h[b * H_ + e] = h;
  g_c[b * H_ + e] = c;
  g_xcat[b * KX_ + E_ + H_ + e] = h;
}

// ---------------- finish body (argmax/done/out/emb feedback) -------------------------
__device__ void finish_body(const float* __restrict__ emb,
                            float* __restrict__ out, int fstep) {
  const int t = threadIdx.x;
  __shared__ float rmax[B_];
  __shared__ int ridx[B_];
  __shared__ int s_done_prev;
  if (t == 0) s_done_prev = g_done;
  if (t < B_) {
    const float* pr = g_preds + t * V_;
    float m = pr[0];
    int mi = 0;
#pragma unroll
    for (int v = 1; v < V_; v++) {
      const float x = pr[v];
      if (x > m) { m = x; mi = v; }
    }
    rmax[t] = m;
    ridx[t] = mi;
  }
  __syncthreads();
  if (t == 0) {
    float bm = rmax[0];
    int bb2 = 0;
    for (int i = 1; i < B_; i++)
      if (rmax[i] > bm) { bm = rmax[i]; bb2 = i; }
    const int flat = bb2 * V_ + ridx[bb2];
    g_done = s_done_prev | (flat == 69);  // END_TOK
  }
  __syncthreads();
  const int dprev = s_done_prev;
  for (int idx = t; idx < B_ * V_; idx += 1024) {
    const int b = idx / V_, v = idx % V_;
    out[(size_t)b * (T_ * V_) + (size_t)fstep * V_ + v] = dprev ? 0.f : g_preds[idx];
  }
  for (int idx = t; idx < B_ * E_; idx += 1024) {
    const int b = idx >> 8, i = idx & 255;
    g_xcat[b * KX_ + i] = emb[ridx[b] * E_ + i];
  }
}

// ---------------- persistent phases ----------------
__device__ void phaseA(int blk, int step, const float* __restrict__ emb,
                       float* __restrict__ out) {
  if (blk < 48) {                         // hproj = h @ [Wd|Wb], 6 n-tiles x 8 k-slots
    const int nt = blk >> 3, z = blk & 7;
    gemm128(g_h, H_, g_Whb, NHP_, g_hproj + (size_t)z * B_ * NHP_,
            64, z * 64, nt * 128);
  } else if (blk < 112) {                 // gates_p1 = h @ Whh, 16 n-tiles x 4 k-slots
    const int u = blk - 48;
    const int nt = u >> 2, z = u & 3;
    gemm128(g_h, H_, g_Wcat + (size_t)768 * G4_, G4_,
            g_gates + (size_t)z * B_ * G4_, 128, z * 128, nt * 128);
  } else if (blk == NBLK - 1) {
    if (step > 0) finish_body(emb, out, step - 1);
  }
}

__device__ void phaseB(const float* __restrict__ wf, const float* __restrict__ bfp,
                       const float* __restrict__ bd) {
  const int blk = blockIdx.x;
  const int t = threadIdx.x;
  int r0 = blk * ROWS_PER_BLK;
  const int r1 = min(B_ * P_, r0 + ROWS_PER_BLK);
  __shared__ float att2_s[A_];
  __shared__ float wf_s[A_];
  __shared__ float s_bf;
  const int wid = t >> 5, lane = t & 31;
  while (r0 < r1) {
    const int b = r0 / P_;
    const int send = min(r1, (b + 1) * P_);
    __syncthreads();
    if (t == 0) s_bf = bfp[0];
    if (t < A_) {
      float v = bd[t];
#pragma unroll
      for (int z = 0; z < NZH_; z++) v += g_hproj[z * B_ * NHP_ + b * NHP_ + t];
      att2_s[t] = v;
      wf_s[t] = wf[t];
    }
    __syncthreads();
    for (int r = r0 + wid; r < send; r += 32) {
      const float4* ap = reinterpret_cast<const float4*>(g_att1 + (size_t)r * A_);
      const float4 v0 = ap[lane];
      const float4 v1 = ap[lane + 32];
      const int a0 = lane * 4;
      const int a1 = 128 + lane * 4;
      float s = 0.f;
      s = fmaf(fmaxf(v0.x + att2_s[a0 + 0], 0.f), wf_s[a0 + 0], s);
      s = fmaf(fmaxf(v0.y + att2_s[a0 + 1], 0.f), wf_s[a0 + 1], s);
      s = fmaf(fmaxf(v0.z + att2_s[a0 + 2], 0.f), wf_s[a0 + 2], s);
      s = fmaf(fmaxf(v0.w + att2_s[a0 + 3], 0.f), wf_s[a0 + 3], s);
      s = fmaf(fmaxf(v1.x + att2_s[a1 + 0], 0.f), wf_s[a1 + 0], s);
      s = fmaf(fmaxf(v1.y + att2_s[a1 + 1], 0.f), wf_s[a1 + 1], s);
      s = fmaf(fmaxf(v1.z + att2_s[a1 + 2], 0.f), wf_s[a1 + 2], s);
      s = fmaf(fmaxf(v1.w + att2_s[a1 + 3], 0.f), wf_s[a1 + 3], s);
      s = warp_sum(s);
      if (lane == 0) g_e[r] = s + s_bf;
    }
    r0 = send;
  }
}

__device__ void phaseC(const float* __restrict__ enc, const float* __restrict__ bb) {
  const int blk = blockIdx.x;
  const int t = threadIdx.x;
  const int u0 = (blk * 512) / NBLK;
  const int u1 = ((blk + 1) * 512) / NBLK;
  __shared__ float e_s[P_];
  __shared__ float red_s[32];
  __shared__ float part_s[1024];
  __shared__ float hg_s[128];
  __shared__ float s_inv_sh;
  const int wid = t >> 5, lane = t & 31;
  int bc = -1;
  for (int u = u0; u < u1; u++) {
    const int b = u >> 2, q = u & 3;
    if (b != bc) {
      bc = b;
      __syncthreads();
      if (t < P_) e_s[t] = g_e[b * P_ + t];
      __syncthreads();
      float lm = -3.402823466e38f;
      if (t < P_) lm = e_s[t];
      lm = warp_max(lm);
      if (lane == 0) red_s[wid] = lm;
      __syncthreads();
      if (wid == 0) {
        const float m = warp_max(red_s[lane]);
        if (lane == 0) red_s[0] = m;
      }
      __syncthreads();
      const float smax = red_s[0];
      float ls = 0.f;
      if (t < P_) {
        const float ex = expf(e_s[t] - smax);
        e_s[t] = ex;
        ls = ex;
      }
      __syncthreads();
      ls = warp_sum(ls);
      if (lane == 0) red_s[wid] = ls;
      __syncthreads();
      if (wid == 0) {
        const float sm = warp_sum(red_s[lane]);
        if (lane == 0) s_inv_sh = 1.f / sm;
      }
      __syncthreads();
    }
    __syncthreads();
    if (t < 128) {
      const int j = q * 128 + t;
      float x = bb[j];
#pragma unroll
      for (int z = 0; z < NZH_; z++) x += g_hproj[z * B_ * NHP_ + b * NHP_ + A_ + j];
      hg_s[t] = sigf(x);
    }
    const int j = q * 128 + (t & 127);
    const int ph = t >> 7;  // 0..7
    const float* encb = enc + (size_t)b * (P_ * ENC_) + j;
    float acc = 0.f;
    int p = ph;
    for (; p + 24 < P_; p += 32) {
      float v[4];
#pragma unroll
      for (int uu = 0; uu < 4; uu++) v[uu] = encb[(size_t)(p + 8 * uu) * ENC_];
#pragma unroll
      for (int uu = 0; uu < 4; uu++) acc = fmaf(e_s[p + 8 * uu], v[uu], acc);
    }
    for (; p < P_; p += 8) acc = fmaf(e_s[p], encb[(size_t)p * ENC_], acc);
    part_s[t] = acc;
    __syncthreads();
    if (t < 128) {
      float awe = 0.f;
#pragma unroll
      for (int g = 0; g < 8; g++) awe += part_s[t + 128 * g];
      awe *= s_inv_sh;
      g_xcat[b * KX_ + E_ + q * 128 + t] = hg_s[t] * awe;
    }
  }
}

__device__ void phaseD(int blk) {
  if (blk >= 128) return;                 // 16 n-tiles x 8 k-slots, K = 768
  const int nt = blk >> 3, z = blk & 7;
  gemm128(g_xcat, KX_, g_Wcat, G4_,
          g_gates + (size_t)(NZG1_ + z) * B_ * G4_, 96, z * 96, nt * 128);
}

__device__ void phaseE(const float* __restrict__ bih, const float* __restrict__ bhh,
                       const float* __restrict__ bfc) {
  const int b = blockIdx.x;
  if (b >= B_) return;
  const int t = threadIdx.x;
  __shared__ float hs[H_];
  if (t < H_) {
    const int j = t;
    float gi = bih[j] + bhh[j];
    float gf = bih[j + 512] + bhh[j + 512];
    float gg = bih[j + 1024] + bhh[j + 1024];
    float go = bih[j + 1536] + bhh[j + 1536];
#pragma unroll
    for (int z = 0; z < NZT_; z++) {
      const float* q = g_gates + (size_t)(z * B_ + b) * G4_;
      gi += q[j];
      gf += q[j + 512];
      gg += q[j + 1024];
      go += q[j + 1536];
    }
    const float c  = g_c[b * H_ + j];
    const float cn = sigf(gf) * c + sigf(gi) * tanhf(gg);
    const float hn = sigf(go) * tanhf(cn);
    g_c[b * H_ + j] = cn;
    g_h[b * H_ + j] = hn;
    g_xcat[b * KX_ + E_ + H_ + j] = hn;
    hs[j] = hn;
  }
  __syncthreads();
  if (t < 512) {
    const int wid = t >> 5, lane = t & 31;
    for (int v = wid; v < V_; v += 16) {
      const float* w = g_WfcT + v * H_;
      float s = 0.f;
#pragma unroll 4
      for (int k = lane; k < H_; k += 32) s = fmaf(hs[k], w[k], s);
      s = warp_sum(s);
      if (lane == 0) g_preds[b * V_ + v] = s + bfc[v];
    }
  }
}

// ---------------- the persistent decode kernel ----------------
__global__ void __launch_bounds__(1024, 1) decode_kernel(
    const float* __restrict__ enc, const float* __restrict__ emb,
    const float* __restrict__ wf, const float* __restrict__ bf,
    const float* __restrict__ bd, const float* __restrict__ bb,
    const float* __restrict__ bih, const float* __restrict__ bhh,
    const float* __restrict__ bfc, float* __restrict__ out) {
  const int blk = blockIdx.x;
  for (int step = 0; step < T_; step++) {
    phaseA(blk, step, emb, out);
    grid_sync();
    phaseB(wf, bf, bd);
    grid_sync();
    phaseC(enc, bb);
    grid_sync();
    phaseD(blk);
    grid_sync();
    phaseE(bih, bhh, bfc);
    grid_sync();
  }
  if (blk == NBLK - 1) finish_body(emb, out, T_ - 1);
}

// ---------------- launch ----------------
extern "C" void kernel_launch(void* const* d_in, const int* in_sizes, int n_in,
                              void* d_out, int out_size) {
  const float* enc = (const float*)d_in[0];
  const float* emb = (const float*)d_in[1];
  const float* We  = (const float*)d_in[2];
  const float* be  = (const float*)d_in[3];
  const float* Wd  = (const float*)d_in[4];
  const float* bd  = (const float*)d_in[5];
  const float* wf  = (const float*)d_in[6];
  const float* bf  = (const float*)d_in[7];
  const float* Wh0 = (const float*)d_in[8];
  const float* bh0 = (const float*)d_in[9];
  const float* Wc0 = (const float*)d_in[10];
  const float* bc0 = (const float*)d_in[11];
  const float* Wb  = (const float*)d_in[12];
  const float* bb  = (const float*)d_in[13];
  const float* Wih = (const float*)d_in[14];
  const float* Whh = (const float*)d_in[15];
  const float* bih = (const float*)d_in[16];
  const float* bhh = (const float*)d_in[17];
  const float* Wfc = (const float*)d_in[18];
  const float* bfc = (const float*)d_in[19];
  float* out = (float*)d_out;

  float *p_att1, *p_Wcat;
  cudaGetSymbolAddress((void**)&p_att1, g_att1);
  cudaGetSymbolAddress((void**)&p_Wcat, g_Wcat);

  // concat [Wih ; Whh] -> Wcat (async D2D copies; capture-legal)
  cudaMemcpyAsync(p_Wcat, Wih, sizeof(float) * (size_t)768 * G4_,
                  cudaMemcpyDeviceToDevice, 0);
  cudaMemcpyAsync(p_Wcat + (size_t)768 * G4_, Whh, sizeof(float) * (size_t)512 * G4_,
                  cudaMemcpyDeviceToDevice, 0);

  prep_weights<<<1536, 256>>>(Wd, Wb, Wfc);
  init_kernel<<<B_, 256>>>(emb);
  mean_init_kernel<<<B_, 512>>>(enc, Wh0, bh0, Wc0, bc0);

  // att1 = enc @ We + be : M=80000, N=256, K=512 (fp32, at FFMA issue roofline)
  gemm64<<<dim3(256 / 64, (B_ * P_) / 64, 1), 256>>>(enc, 512, We, p_att1, be,
                                                     B_ * P_, 256, 512);

  // whole 70-step decode in ONE persistent kernel (software grid barriers)
  decode_kernel<<<NBLK, 1024>>>(enc, emb, wf, bf, bd, bb, bih, bhh, bfc, out);
}